// round 2
// baseline (speedup 1.0000x reference)
#include <cuda_runtime.h>

// LayerwiseLowRankUplift: out = z + U_l (V_l^T z), grouped by layer.
// B=2048, H=2048, R=64, NL=32. Pure fp32, grouped-GEMM formulation.

constexpr int B  = 2048;
constexpr int H  = 2048;
constexpr int R  = 64;
constexpr int NL = 32;

constexpr int TS     = 32;          // samples per tile
constexpr int ST     = 4;           // sample-tile grid extent (grid-strided beyond)
constexpr int KPART  = 4;           // split-K factor for pass 1
constexpr int KSLICE = H / KPART;   // 512
constexpr int HTILE  = 128;         // h per tile in pass 2

// ---------------- device scratch (no allocation allowed) ----------------
__device__ int d_count[NL];
__device__ int d_offset[NL + 1];
__device__ int d_cursor[NL];
__device__ int d_order[B];
__device__ __align__(16) float d_projp[(size_t)KPART * B * R];  // 2 MB partials

// ---------------- grouping kernels ----------------
__global__ void k_init() {
    int t = threadIdx.x;
    if (t < NL) { d_count[t] = 0; d_cursor[t] = 0; }
}

__global__ void k_count(const int* __restrict__ lid) {
    int i = blockIdx.x * blockDim.x + threadIdx.x;
    if (i < B) atomicAdd(&d_count[lid[i]], 1);
}

__global__ void k_scan() {
    int acc = 0;
    for (int i = 0; i < NL; i++) { d_offset[i] = acc; acc += d_count[i]; }
    d_offset[NL] = acc;
}

__global__ void k_scatter(const int* __restrict__ lid) {
    int i = blockIdx.x * blockDim.x + threadIdx.x;
    if (i < B) {
        int l = lid[i];
        int pos = d_offset[l] + atomicAdd(&d_cursor[l], 1);
        d_order[pos] = i;
    }
}

// ---------------- pass 1: proj_part[kp][slot][r] = sum_{h in slice} v[l][h][r] * z[b][h]
__global__ __launch_bounds__(256) void k_pass1(const float* __restrict__ z,
                                               const float* __restrict__ v) {
    const int l     = blockIdx.z;
    const int kpart = blockIdx.y;
    const int start = d_offset[l];
    const int cnt   = d_offset[l + 1] - start;
    const int t     = threadIdx.x;
    const int sidx  = t & 15;   // 16 sample-pairs (2 samples each)
    const int ridx  = t >> 4;   // 16 r-quads (4 r each)
    const int kbase = kpart * KSLICE;

    __shared__ __align__(16) float zs[32][34];   // [k][s], pad 34: float2-aligned, low conflict
    __shared__ __align__(16) float vs[32][68];   // [k][r], pad 68: float4-aligned
    __shared__ int ord[TS];

    for (int s0 = blockIdx.x * TS; s0 < cnt; s0 += ST * TS) {
        if (t < TS) ord[t] = (s0 + t < cnt) ? d_order[start + s0 + t] : -1;
        __syncthreads();

        float acc[2][4] = {};

        for (int kk = 0; kk < KSLICE; kk += 32) {
            // load z tile (gathered rows), transposed to [k][s]
            #pragma unroll
            for (int i = 0; i < 4; i++) {
                int idx = t + i * 256;
                int k = idx & 31, s = idx >> 5;
                int b = ord[s];
                zs[k][s] = (b >= 0) ? z[(size_t)b * H + kbase + kk + k] : 0.f;
            }
            // load v tile [k][r]
            #pragma unroll
            for (int i = 0; i < 8; i++) {
                int idx = t + i * 256;
                int r = idx & 63, k = idx >> 6;
                vs[k][r] = v[((size_t)l * H + kbase + kk + k) * R + r];
            }
            __syncthreads();

            #pragma unroll
            for (int k = 0; k < 32; k++) {
                float2 zf = *(const float2*)&zs[k][2 * sidx];
                float4 vf = *(const float4*)&vs[k][4 * ridx];
                acc[0][0] += zf.x * vf.x; acc[0][1] += zf.x * vf.y;
                acc[0][2] += zf.x * vf.z; acc[0][3] += zf.x * vf.w;
                acc[1][0] += zf.y * vf.x; acc[1][1] += zf.y * vf.y;
                acc[1][2] += zf.y * vf.z; acc[1][3] += zf.y * vf.w;
            }
            __syncthreads();
        }

        #pragma unroll
        for (int i = 0; i < 2; i++) {
            int s = 2 * sidx + i;
            if (s0 + s < cnt) {
                float4 val = make_float4(acc[i][0], acc[i][1], acc[i][2], acc[i][3]);
                *(float4*)&d_projp[((size_t)kpart * B + (start + s0 + s)) * R + 4 * ridx] = val;
            }
        }
        __syncthreads();  // protect ord/smem before next stile iteration
    }
}

// ---------------- pass 2: out[b][h] = z[b][h] + sum_r u[l][h][r] * proj[slot][r]
__global__ __launch_bounds__(256) void k_pass2(const float* __restrict__ z,
                                               const float* __restrict__ u,
                                               float* __restrict__ out) {
    const int l     = blockIdx.z;
    const int h0    = blockIdx.x * HTILE;
    const int start = d_offset[l];
    const int cnt   = d_offset[l + 1] - start;
    if (cnt == 0) return;
    const int t    = threadIdx.x;
    const int sidx = t & 7;    // 8 positions x 4 samples = 32
    const int hidx = t >> 3;   // 32 positions x 4 h = 128

    __shared__ __align__(16) float ps[TS][65];      // [s][r], pad 65: conflict-free reads
    __shared__ __align__(16) float us[HTILE][72];   // [h][r], pad 72: float4-aligned, conflict-free
    __shared__ int ord[TS];

    // load u tile once per block (independent of sample tile)
    #pragma unroll
    for (int i = 0; i < 8; i++) {
        int fidx = t + i * 256;            // 128 rows x 16 float4
        int h = fidx >> 4, c = fidx & 15;
        float4 val = *(const float4*)&u[((size_t)l * H + h0 + h) * R + 4 * c];
        *(float4*)&us[h][4 * c] = val;
    }

    for (int s0 = blockIdx.y * TS; s0 < cnt; s0 += ST * TS) {
        if (t < TS) ord[t] = (s0 + t < cnt) ? d_order[start + s0 + t] : -1;
        // load proj tile, summing the 4 split-K partials (fixed order -> deterministic)
        #pragma unroll
        for (int i = 0; i < 8; i++) {
            int idx = t + i * 256;
            int r = idx & 63, s = idx >> 6;
            float val = 0.f;
            if (s0 + s < cnt) {
                size_t slot = (size_t)(start + s0 + s);
                val = d_projp[slot * R + r]
                    + d_projp[(size_t)B * R + slot * R + r]
                    + d_projp[2 * (size_t)B * R + slot * R + r]
                    + d_projp[3 * (size_t)B * R + slot * R + r];
            }
            ps[s][r] = val;
        }
        __syncthreads();

        float acc[4][4] = {};
        #pragma unroll 8
        for (int r = 0; r < R; r++) {
            float pv[4], uv[4];
            #pragma unroll
            for (int i = 0; i < 4; i++) pv[i] = ps[4 * sidx + i][r];
            #pragma unroll
            for (int j = 0; j < 4; j++) uv[j] = us[4 * hidx + j][r];
            #pragma unroll
            for (int i = 0; i < 4; i++)
                #pragma unroll
                for (int j = 0; j < 4; j++)
                    acc[i][j] += pv[i] * uv[j];
        }

        // epilogue: out = z + delta, gathered row stores (contiguous float4 per row)
        #pragma unroll
        for (int i = 0; i < 4; i++) {
            int s = 4 * sidx + i;
            int b = ord[s];
            if (b >= 0) {
                size_t off = (size_t)b * H + h0 + 4 * hidx;
                float4 zv = *(const float4*)&z[off];
                float4 o  = make_float4(zv.x + acc[i][0], zv.y + acc[i][1],
                                        zv.z + acc[i][2], zv.w + acc[i][3]);
                *(float4*)&out[off] = o;
            }
        }
        __syncthreads();  // protect ps/ord before next stile iteration
    }
}

// ---------------- launcher ----------------
extern "C" void kernel_launch(void* const* d_in, const int* in_sizes, int n_in,
                              void* d_out, int out_size) {
    const float* z   = (const float*)d_in[0];
    const int*   lid = (const int*)d_in[1];
    const float* u   = (const float*)d_in[2];
    const float* v   = (const float*)d_in[3];
    float* out = (float*)d_out;

    k_init<<<1, 32>>>();
    k_count<<<(B + 255) / 256, 256>>>(lid);
    k_scan<<<1, 1>>>();
    k_scatter<<<(B + 255) / 256, 256>>>(lid);
    k_pass1<<<dim3(ST, KPART, NL), 256>>>(z, v);
    k_pass2<<<dim3(H / HTILE, ST, NL), 256>>>(z, u, out);
}